// round 13
// baseline (speedup 1.0000x reference)
#include <cuda_runtime.h>

#define N_NODES 100000
#define F_IN 512
#define HID 16
#define CLS 7
#define HID2 8
#define E_MAX 3400000
#define NB_NODE 391          // ceil(100000/256)

typedef unsigned long long ull;

// ---------------- device scratch ----------------
__device__ int   g_degi[N_NODES];
__device__ int   g_off [N_NODES + 1];
__device__ int   g_cur [N_NODES];
__device__ int   g_bsum[512];
__device__ float g_dinv[N_NODES];
__device__ __align__(16) float g_h1 [N_NODES * HID];
__device__ __align__(16) float g_h2 [N_NODES * HID2];
__device__ __align__(16) uint2 g_csr[E_MAX];           // {src, bits(weight)}
__device__ int g_is64;

// ---- f32x2 helpers (Blackwell packed fp32 pipe) ----
__device__ __forceinline__ ull fma2(ull a, ull b, ull c) {
    ull d;
    asm("fma.rn.f32x2 %0, %1, %2, %3;" : "=l"(d) : "l"(a), "l"(b), "l"(c));
    return d;
}
__device__ __forceinline__ ull pack2(float a) {
    ull p;
    asm("mov.b64 %0, {%1, %1};" : "=l"(p) : "f"(a));
    return p;
}
__device__ __forceinline__ void unpack2(ull p, float& lo, float& hi) {
    asm("mov.b64 {%0, %1}, %2;" : "=f"(lo), "=f"(hi) : "l"(p));
}

union F4U { float4 f; ull u[2]; };

// ---------------- detect dtype + zero degrees (fused) ----------------
__global__ void k_detect_zero(const unsigned int* __restrict__ w) {
    int i = blockIdx.x * blockDim.x + threadIdx.x;
    if (i < N_NODES) g_degi[i] = 0;
    if (i == 0) {
        int all0 = 1;
        #pragma unroll 1
        for (int k = 0; k < 64; k++) {
            long idx = 2L * k * 50001L + 1L;
            if (w[idx] != 0u) all0 = 0;
        }
        g_is64 = all0;
    }
}

// ---------------- degree count (int atomics) ----------------
__global__ void k_deg(const void* __restrict__ ei, int E) {
    int i = blockIdx.x * blockDim.x + threadIdx.x;
    if (i >= E) return;
    int dst;
    if (g_is64) dst = (int)__ldg(&((const long long*)ei)[(size_t)E + i]);
    else        dst = __ldg(&((const int*)ei)[(size_t)E + i]);
    atomicAdd(&g_degi[dst], 1);
}

// ---------------- scan stage 1: per-block exclusive scan ----------------
__global__ void k_scan1() {
    __shared__ int s[256];
    int b = blockIdx.x, t = threadIdx.x;
    int i = b * 256 + t;
    int v = (i < N_NODES) ? g_degi[i] : 0;
    s[t] = v; __syncthreads();
    #pragma unroll
    for (int d = 1; d < 256; d <<= 1) {
        int add = (t >= d) ? s[t - d] : 0;
        __syncthreads();
        s[t] += add;
        __syncthreads();
    }
    if (i < N_NODES) g_off[i] = s[t] - v;   // local exclusive
    if (t == 255) g_bsum[b] = s[255];
}

// ---------------- scan stage 2 (block offsets per-block) + dinv ----------
__global__ void k_scan3(int E) {
    __shared__ int sb[256];
    int t = threadIdx.x, b = blockIdx.x;
    int part = 0;
    for (int j = t; j < b; j += 256) part += g_bsum[j];
    sb[t] = part; __syncthreads();
    #pragma unroll
    for (int d = 128; d > 0; d >>= 1) {
        if (t < d) sb[t] += sb[t + d];
        __syncthreads();
    }
    int boff = sb[0];
    int i = b * 256 + t;
    if (i < N_NODES) {
        int off = g_off[i] + boff;
        g_off[i] = off;
        g_cur[i] = off;
        g_dinv[i] = rsqrtf((float)(g_degi[i] + 1));  // +1 self loop
        if (i == N_NODES - 1) g_off[N_NODES] = E;
    }
}

// ---------------- CSR build: scatter {src, weight} by dst ----------------
__global__ void k_build(const void* __restrict__ ei, int E) {
    int i = blockIdx.x * blockDim.x + threadIdx.x;
    if (i >= E) return;
    int src, dst;
    if (g_is64) {
        const long long* e = (const long long*)ei;
        src = (int)__ldg(&e[i]); dst = (int)__ldg(&e[(size_t)E + i]);
    } else {
        const int* e = (const int*)ei;
        src = __ldg(&e[i]); dst = __ldg(&e[(size_t)E + i]);
    }
    float w = __ldg(&g_dinv[src]) * __ldg(&g_dinv[dst]);
    int pos = atomicAdd(&g_cur[dst], 1);
    g_csr[pos] = make_uint2((unsigned)src, __float_as_uint(w));
}

// ------ GEMM1: h1 = x @ W1, 2 rows/thread, f32x2, high-occupancy ---------
#define G1_TPB  128
#define G1_ROWS 256            // rows per block = 2 * G1_TPB
#define KC      32
#define XS2     36             // 32 + pad (stride ≡ 4 mod 32: conflict-free)
__global__ void __launch_bounds__(G1_TPB)
k_gemm1(const float* __restrict__ x, const float* __restrict__ W1) {
    __shared__ float xs[G1_ROWS * XS2];            // 36 KB
    __shared__ __align__(16) float ws[KC * HID];   // 2 KB

    int t = threadIdx.x;
    int rowbase = blockIdx.x * G1_ROWS;

    ull acc[2][8];                                  // 8 f32x2 pairs per row
    #pragma unroll
    for (int r = 0; r < 2; r++)
        #pragma unroll
        for (int j = 0; j < 8; j++) acc[r][j] = 0ULL;

    #pragma unroll 1
    for (int ch = 0; ch < F_IN / KC; ch++) {
        // W chunk: KC*HID = 512 floats = 128 float4, 1 per thread
        {
            const float4* wsrc = (const float4*)(W1 + ch * KC * HID);
            ((float4*)ws)[t] = __ldg(&wsrc[t]);
        }
        // x tile coalesced: 256 rows x 32 cols = 2048 float4, 16 per thread
        #pragma unroll
        for (int i = 0; i < 16; i++) {
            int f   = t + i * G1_TPB;
            int row = f >> 3;                       // 8 float4 per row
            int c4  = f & 7;
            int grow = rowbase + row;
            if (grow >= N_NODES) grow = N_NODES - 1;
            float4 v = __ldg((const float4*)(x + (size_t)grow * F_IN + ch * KC) + c4);
            *(float4*)&xs[row * XS2 + c4 * 4] = v;
        }
        __syncthreads();

        #pragma unroll
        for (int k4 = 0; k4 < KC / 4; k4++) {
            float4 xv0 = *(const float4*)&xs[(t          ) * XS2 + k4 * 4];
            float4 xv1 = *(const float4*)&xs[(t + G1_TPB ) * XS2 + k4 * 4];
            #pragma unroll
            for (int kk = 0; kk < 4; kk++) {
                const float4* wq = (const float4*)&ws[(k4 * 4 + kk) * HID];
                F4U wa, wb, wc, wd;
                wa.f = wq[0]; wb.f = wq[1]; wc.f = wq[2]; wd.f = wq[3];
                ull p0 = pack2(((const float*)&xv0)[kk]);
                ull p1 = pack2(((const float*)&xv1)[kk]);
                acc[0][0] = fma2(p0, wa.u[0], acc[0][0]);
                acc[0][1] = fma2(p0, wa.u[1], acc[0][1]);
                acc[0][2] = fma2(p0, wb.u[0], acc[0][2]);
                acc[0][3] = fma2(p0, wb.u[1], acc[0][3]);
                acc[0][4] = fma2(p0, wc.u[0], acc[0][4]);
                acc[0][5] = fma2(p0, wc.u[1], acc[0][5]);
                acc[0][6] = fma2(p0, wd.u[0], acc[0][6]);
                acc[0][7] = fma2(p0, wd.u[1], acc[0][7]);
                acc[1][0] = fma2(p1, wa.u[0], acc[1][0]);
                acc[1][1] = fma2(p1, wa.u[1], acc[1][1]);
                acc[1][2] = fma2(p1, wb.u[0], acc[1][2]);
                acc[1][3] = fma2(p1, wb.u[1], acc[1][3]);
                acc[1][4] = fma2(p1, wc.u[0], acc[1][4]);
                acc[1][5] = fma2(p1, wc.u[1], acc[1][5]);
                acc[1][6] = fma2(p1, wd.u[0], acc[1][6]);
                acc[1][7] = fma2(p1, wd.u[1], acc[1][7]);
            }
        }
        __syncthreads();
    }

    #pragma unroll
    for (int r = 0; r < 2; r++) {
        int row = rowbase + t + r * G1_TPB;
        if (row < N_NODES) {
            float4* o = (float4*)(g_h1 + (size_t)row * HID);
            #pragma unroll
            for (int q = 0; q < 4; q++) {
                float a, b, c, d;
                unpack2(acc[r][q * 2],     a, b);
                unpack2(acc[r][q * 2 + 1], c, d);
                o[q] = make_float4(a, b, c, d);
            }
        }
    }
}

// ------- gather layer 1 + selfloop + bias + relu + GEMM2 -> h2 (fused) -----
#define GTPB 256
__global__ void k_gather1(const float* __restrict__ b1, const float* __restrict__ W2) {
    __shared__ float Ws2[HID * HID2];   // W2 padded to 8 cols (col 7 = 0)
    __shared__ float b1s[HID];
    if (threadIdx.x < HID * HID2) {
        int k = threadIdx.x >> 3, j = threadIdx.x & 7;
        Ws2[threadIdx.x] = (j < CLS) ? __ldg(&W2[k * CLS + j]) : 0.0f;
    }
    if (threadIdx.x < HID) b1s[threadIdx.x] = __ldg(&b1[threadIdx.x]);
    __syncthreads();

    int warp = (blockIdx.x * GTPB + threadIdx.x) >> 5;
    if (warp >= N_NODES) return;
    int lane = threadIdx.x & 31;
    int eslot = lane >> 2;          // 0..7
    int q     = lane & 3;           // float4 chunk 0..3

    int beg = __ldg(&g_off[warp]);
    int end = __ldg(&g_off[warp + 1]);

    float4 acc = make_float4(0.f, 0.f, 0.f, 0.f);
    for (int e = beg + eslot; e < end; e += 8) {
        uint2 ent = __ldg(&g_csr[e]);
        float w = __uint_as_float(ent.y);
        float4 v = __ldg((const float4*)(g_h1 + (size_t)ent.x * HID) + q);
        acc.x = fmaf(v.x, w, acc.x);
        acc.y = fmaf(v.y, w, acc.y);
        acc.z = fmaf(v.z, w, acc.z);
        acc.w = fmaf(v.w, w, acc.w);
    }
    #pragma unroll
    for (int m = 4; m <= 16; m <<= 1) {
        acc.x += __shfl_xor_sync(0xffffffffu, acc.x, m);
        acc.y += __shfl_xor_sync(0xffffffffu, acc.y, m);
        acc.z += __shfl_xor_sync(0xffffffffu, acc.z, m);
        acc.w += __shfl_xor_sync(0xffffffffu, acc.w, m);
    }
    float dv = __ldg(&g_dinv[warp]);
    float d2 = dv * dv;
    float4 hv = __ldg((const float4*)(g_h1 + (size_t)warp * HID) + q);
    float4 r4;
    r4.x = fmaxf(acc.x + d2 * hv.x + b1s[q * 4 + 0], 0.0f);
    r4.y = fmaxf(acc.y + d2 * hv.y + b1s[q * 4 + 1], 0.0f);
    r4.z = fmaxf(acc.z + d2 * hv.z + b1s[q * 4 + 2], 0.0f);
    r4.w = fmaxf(acc.w + d2 * hv.w + b1s[q * 4 + 3], 0.0f);

    // GEMM2 within warp: lane j (j = lane & 7) computes output column j
    float racc = 0.0f;
    int j = lane & 7;
    #pragma unroll
    for (int qq = 0; qq < 4; qq++) {
        float rx = __shfl_sync(0xffffffffu, r4.x, qq);
        float ry = __shfl_sync(0xffffffffu, r4.y, qq);
        float rz = __shfl_sync(0xffffffffu, r4.z, qq);
        float rw = __shfl_sync(0xffffffffu, r4.w, qq);
        racc = fmaf(rx, Ws2[(qq * 4 + 0) * HID2 + j], racc);
        racc = fmaf(ry, Ws2[(qq * 4 + 1) * HID2 + j], racc);
        racc = fmaf(rz, Ws2[(qq * 4 + 2) * HID2 + j], racc);
        racc = fmaf(rw, Ws2[(qq * 4 + 3) * HID2 + j], racc);
    }
    if (lane < 8) g_h2[(size_t)warp * HID2 + lane] = racc;   // col 7 -> 0 via pad
}

// ---------------- gather layer 2 + finalize -> out ----------------
__global__ void k_gather2(const float* __restrict__ b2, float* __restrict__ out) {
    int warp = (blockIdx.x * GTPB + threadIdx.x) >> 5;
    if (warp >= N_NODES) return;
    int lane = threadIdx.x & 31;
    int eslot = lane >> 1;          // 0..15
    int half  = lane & 1;

    int beg = __ldg(&g_off[warp]);
    int end = __ldg(&g_off[warp + 1]);

    float4 acc = make_float4(0.f, 0.f, 0.f, 0.f);
    for (int e = beg + eslot; e < end; e += 16) {
        uint2 ent = __ldg(&g_csr[e]);
        float w = __uint_as_float(ent.y);
        float4 v = __ldg((const float4*)(g_h2 + (size_t)ent.x * HID2) + half);
        acc.x = fmaf(v.x, w, acc.x);
        acc.y = fmaf(v.y, w, acc.y);
        acc.z = fmaf(v.z, w, acc.z);
        acc.w = fmaf(v.w, w, acc.w);
    }
    #pragma unroll
    for (int m = 2; m <= 16; m <<= 1) {
        acc.x += __shfl_xor_sync(0xffffffffu, acc.x, m);
        acc.y += __shfl_xor_sync(0xffffffffu, acc.y, m);
        acc.z += __shfl_xor_sync(0xffffffffu, acc.z, m);
        acc.w += __shfl_xor_sync(0xffffffffu, acc.w, m);
    }
    if (lane < 2) {
        float dv = __ldg(&g_dinv[warp]);
        float d2 = dv * dv;
        float4 hv = *((const float4*)(g_h2 + (size_t)warp * HID2) + half);
        float o0 = acc.x + d2 * hv.x;
        float o1 = acc.y + d2 * hv.y;
        float o2 = acc.z + d2 * hv.z;
        float o3 = acc.w + d2 * hv.w;
        float* op = out + (size_t)warp * CLS + half * 4;
        if (half == 0) {
            op[0] = o0 + __ldg(&b2[0]);
            op[1] = o1 + __ldg(&b2[1]);
            op[2] = o2 + __ldg(&b2[2]);
            op[3] = o3 + __ldg(&b2[3]);
        } else {
            op[0] = o0 + __ldg(&b2[4]);
            op[1] = o1 + __ldg(&b2[5]);
            op[2] = o2 + __ldg(&b2[6]);
        }
    }
}

// ---------------- launch: fork-join; gemm1 issued 4th for ncu capture -----
extern "C" void kernel_launch(void* const* d_in, const int* in_sizes, int n_in,
                              void* d_out, int out_size) {
    const float* x  = (const float*)d_in[0];
    const void*  ei = d_in[1];
    const float* W1 = (const float*)d_in[2];
    const float* b1 = (const float*)d_in[3];
    const float* W2 = (const float*)d_in[4];
    const float* b2 = (const float*)d_in[5];
    float* out = (float*)d_out;

    int E = in_sizes[1] / 2;

    static cudaStream_t s2 = nullptr;
    static cudaEvent_t  e0 = nullptr, e1 = nullptr;
    if (s2 == nullptr) {   // first call is the uncaptured correctness run
        cudaStreamCreateWithFlags(&s2, cudaStreamNonBlocking);
        cudaEventCreateWithFlags(&e0, cudaEventDisableTiming);
        cudaEventCreateWithFlags(&e1, cudaEventDisableTiming);
    }

    const int TPB = 256;
    int nbE  = (E + TPB - 1) / TPB;
    int nbG  = (N_NODES * 32 + GTPB - 1) / GTPB;
    int nbG1 = (N_NODES + G1_ROWS - 1) / G1_ROWS;

    cudaEventRecord(e0, 0);
    cudaStreamWaitEvent(s2, e0, 0);

    // main stream: edge pipeline (first 3 issues), then gemm1 issued 4th
    k_detect_zero<<<NB_NODE, TPB>>>((const unsigned int*)ei);
    k_deg  <<<nbE, TPB>>>(ei, E);
    k_scan1<<<NB_NODE, TPB>>>();

    k_gemm1<<<nbG1, G1_TPB, 0, s2>>>(x, W1);   // 4th issued launch -> ncu target
    cudaEventRecord(e1, s2);

    k_scan3<<<NB_NODE, TPB>>>(E);
    k_build<<<nbE, TPB>>>(ei, E);

    // join: gathers need both h1 (gemm1) and csr (build)
    cudaStreamWaitEvent(0, e1, 0);
    k_gather1<<<nbG, GTPB>>>(b1, W2);
    k_gather2<<<nbG, GTPB>>>(b2, out);
}

// round 14
// speedup vs baseline: 1.2769x; 1.2769x over previous
#include <cuda_runtime.h>

#define N_NODES 100000
#define F_IN 512
#define HID 16
#define CLS 7
#define HID2 8
#define E_MAX 3400000
#define NB_NODE 391          // ceil(100000/256)

typedef unsigned long long ull;

// ---------------- device scratch ----------------
__device__ int   g_degi[N_NODES];
__device__ int   g_off [N_NODES + 1];
__device__ int   g_cur [N_NODES];
__device__ int   g_bsum[512];
__device__ float g_dinv[N_NODES];
__device__ __align__(16) float g_h1 [N_NODES * HID];
__device__ __align__(16) float g_h2 [N_NODES * HID2];
__device__ __align__(16) uint2 g_csr[E_MAX];           // {src, bits(weight)}
__device__ int g_is64;

// ---- f32x2 helpers (Blackwell packed fp32 pipe) ----
__device__ __forceinline__ ull fma2(ull a, ull b, ull c) {
    ull d;
    asm("fma.rn.f32x2 %0, %1, %2, %3;" : "=l"(d) : "l"(a), "l"(b), "l"(c));
    return d;
}
__device__ __forceinline__ ull pack2(float a) {
    ull p;
    asm("mov.b64 %0, {%1, %1};" : "=l"(p) : "f"(a));
    return p;
}
__device__ __forceinline__ void unpack2(ull p, float& lo, float& hi) {
    asm("mov.b64 {%0, %1}, %2;" : "=f"(lo), "=f"(hi) : "l"(p));
}
union F4U { float4 f; ull u[2]; };

// ---- cp.async helpers ----
__device__ __forceinline__ void cp16(void* smem_dst, const void* gmem_src) {
    unsigned s = (unsigned)__cvta_generic_to_shared(smem_dst);
    asm volatile("cp.async.cg.shared.global [%0], [%1], 16;" :: "r"(s), "l"(gmem_src));
}
__device__ __forceinline__ void cp_commit() {
    asm volatile("cp.async.commit_group;");
}
__device__ __forceinline__ void cp_wait1() {
    asm volatile("cp.async.wait_group 1;");
}

// ---------------- detect dtype + zero degrees (fused) ----------------
__global__ void k_detect_zero(const unsigned int* __restrict__ w) {
    int i = blockIdx.x * blockDim.x + threadIdx.x;
    if (i < N_NODES) g_degi[i] = 0;
    if (i == 0) {
        int all0 = 1;
        #pragma unroll 1
        for (int k = 0; k < 64; k++) {
            long idx = 2L * k * 50001L + 1L;
            if (w[idx] != 0u) all0 = 0;
        }
        g_is64 = all0;
    }
}

// ---------------- degree count (int atomics) ----------------
__global__ void k_deg(const void* __restrict__ ei, int E) {
    int i = blockIdx.x * blockDim.x + threadIdx.x;
    if (i >= E) return;
    int dst;
    if (g_is64) dst = (int)__ldg(&((const long long*)ei)[(size_t)E + i]);
    else        dst = __ldg(&((const int*)ei)[(size_t)E + i]);
    atomicAdd(&g_degi[dst], 1);
}

// ---------------- scan stage 1: per-block exclusive scan ----------------
__global__ void k_scan1() {
    __shared__ int s[256];
    int b = blockIdx.x, t = threadIdx.x;
    int i = b * 256 + t;
    int v = (i < N_NODES) ? g_degi[i] : 0;
    s[t] = v; __syncthreads();
    #pragma unroll
    for (int d = 1; d < 256; d <<= 1) {
        int add = (t >= d) ? s[t - d] : 0;
        __syncthreads();
        s[t] += add;
        __syncthreads();
    }
    if (i < N_NODES) g_off[i] = s[t] - v;   // local exclusive
    if (t == 255) g_bsum[b] = s[255];
}

// ---------------- scan stage 2 (block offsets per-block) + dinv ----------
__global__ void k_scan3(int E) {
    __shared__ int sb[256];
    int t = threadIdx.x, b = blockIdx.x;
    int part = 0;
    for (int j = t; j < b; j += 256) part += g_bsum[j];
    sb[t] = part; __syncthreads();
    #pragma unroll
    for (int d = 128; d > 0; d >>= 1) {
        if (t < d) sb[t] += sb[t + d];
        __syncthreads();
    }
    int boff = sb[0];
    int i = b * 256 + t;
    if (i < N_NODES) {
        int off = g_off[i] + boff;
        g_off[i] = off;
        g_cur[i] = off;
        g_dinv[i] = rsqrtf((float)(g_degi[i] + 1));  // +1 self loop
        if (i == N_NODES - 1) g_off[N_NODES] = E;
    }
}

// ---------------- CSR build: scatter {src, weight} by dst ----------------
__global__ void k_build(const void* __restrict__ ei, int E) {
    int i = blockIdx.x * blockDim.x + threadIdx.x;
    if (i >= E) return;
    int src, dst;
    if (g_is64) {
        const long long* e = (const long long*)ei;
        src = (int)__ldg(&e[i]); dst = (int)__ldg(&e[(size_t)E + i]);
    } else {
        const int* e = (const int*)ei;
        src = __ldg(&e[i]); dst = __ldg(&e[(size_t)E + i]);
    }
    float w = __ldg(&g_dinv[src]) * __ldg(&g_dinv[dst]);
    int pos = atomicAdd(&g_cur[dst], 1);
    g_csr[pos] = make_uint2((unsigned)src, __float_as_uint(w));
}

// ---- GEMM1: h1 = x @ W1, cp.async double-buffered, f32x2, 1 row/thread ----
#define G1_TPB  128
#define KC      32
#define NCHUNK  (F_IN / KC)    // 16
#define XS2     36             // 32 + 4 pad: conflict-free LDS.128
__global__ void __launch_bounds__(G1_TPB)
k_gemm1(const float* __restrict__ x, const float* __restrict__ W1) {
    __shared__ __align__(16) float xs[2][G1_TPB * XS2];   // 2 x 18 KB
    __shared__ __align__(16) float ws[2][KC * HID];       // 2 x 2 KB

    int t = threadIdx.x;
    int rowbase = blockIdx.x * G1_TPB;

    ull acc[8];
    #pragma unroll
    for (int j = 0; j < 8; j++) acc[j] = 0ULL;

    // async-load chunk `ch` into buffer `buf`
    auto issue = [&](int ch, int buf) {
        // W chunk: KC*HID = 512 floats = 128 float4, 1 per thread
        cp16(&ws[buf][t * 4], (const float4*)(W1 + ch * KC * HID) + t);
        // x tile: 128 rows x 32 cols = 1024 float4, 8 per thread, coalesced
        #pragma unroll
        for (int i = 0; i < 8; i++) {
            int f   = t + i * G1_TPB;
            int row = f >> 3;              // 8 float4 per row
            int c4  = f & 7;
            int grow = rowbase + row;
            if (grow >= N_NODES) grow = N_NODES - 1;
            cp16(&xs[buf][row * XS2 + c4 * 4],
                 (const float4*)(x + (size_t)grow * F_IN + ch * KC) + c4);
        }
    };

    issue(0, 0);
    cp_commit();

    #pragma unroll 1
    for (int ch = 0; ch < NCHUNK; ch++) {
        if (ch + 1 < NCHUNK) issue(ch + 1, (ch + 1) & 1);
        cp_commit();
        cp_wait1();               // oldest group (chunk ch) complete
        __syncthreads();

        int cb = ch & 1;
        #pragma unroll
        for (int k4 = 0; k4 < KC / 4; k4++) {
            float4 xv = *(const float4*)&xs[cb][t * XS2 + k4 * 4];
            #pragma unroll
            for (int kk = 0; kk < 4; kk++) {
                const float4* wq = (const float4*)&ws[cb][(k4 * 4 + kk) * HID];
                F4U wa, wb, wc, wd;
                wa.f = wq[0]; wb.f = wq[1]; wc.f = wq[2]; wd.f = wq[3];
                ull p = pack2(((const float*)&xv)[kk]);
                acc[0] = fma2(p, wa.u[0], acc[0]);
                acc[1] = fma2(p, wa.u[1], acc[1]);
                acc[2] = fma2(p, wb.u[0], acc[2]);
                acc[3] = fma2(p, wb.u[1], acc[3]);
                acc[4] = fma2(p, wc.u[0], acc[4]);
                acc[5] = fma2(p, wc.u[1], acc[5]);
                acc[6] = fma2(p, wd.u[0], acc[6]);
                acc[7] = fma2(p, wd.u[1], acc[7]);
            }
        }
        __syncthreads();          // protect buffer before next-next overwrite
    }

    int row = rowbase + t;
    if (row < N_NODES) {
        float4* o = (float4*)(g_h1 + (size_t)row * HID);
        #pragma unroll
        for (int q = 0; q < 4; q++) {
            float a, b, c, d;
            unpack2(acc[q * 2],     a, b);
            unpack2(acc[q * 2 + 1], c, d);
            o[q] = make_float4(a, b, c, d);
        }
    }
}

// ------- gather layer 1 + selfloop + bias + relu + GEMM2 -> h2 (fused) -----
#define GTPB 256
__global__ void k_gather1(const float* __restrict__ b1, const float* __restrict__ W2) {
    __shared__ float Ws2[HID * HID2];   // W2 padded to 8 cols (col 7 = 0)
    __shared__ float b1s[HID];
    if (threadIdx.x < HID * HID2) {
        int k = threadIdx.x >> 3, j = threadIdx.x & 7;
        Ws2[threadIdx.x] = (j < CLS) ? __ldg(&W2[k * CLS + j]) : 0.0f;
    }
    if (threadIdx.x < HID) b1s[threadIdx.x] = __ldg(&b1[threadIdx.x]);
    __syncthreads();

    int warp = (blockIdx.x * GTPB + threadIdx.x) >> 5;
    if (warp >= N_NODES) return;
    int lane = threadIdx.x & 31;
    int eslot = lane >> 2;          // 0..7
    int q     = lane & 3;           // float4 chunk 0..3

    int beg = __ldg(&g_off[warp]);
    int end = __ldg(&g_off[warp + 1]);

    float4 acc = make_float4(0.f, 0.f, 0.f, 0.f);
    for (int e = beg + eslot; e < end; e += 8) {
        uint2 ent = __ldg(&g_csr[e]);
        float w = __uint_as_float(ent.y);
        float4 v = __ldg((const float4*)(g_h1 + (size_t)ent.x * HID) + q);
        acc.x = fmaf(v.x, w, acc.x);
        acc.y = fmaf(v.y, w, acc.y);
        acc.z = fmaf(v.z, w, acc.z);
        acc.w = fmaf(v.w, w, acc.w);
    }
    #pragma unroll
    for (int m = 4; m <= 16; m <<= 1) {
        acc.x += __shfl_xor_sync(0xffffffffu, acc.x, m);
        acc.y += __shfl_xor_sync(0xffffffffu, acc.y, m);
        acc.z += __shfl_xor_sync(0xffffffffu, acc.z, m);
        acc.w += __shfl_xor_sync(0xffffffffu, acc.w, m);
    }
    float dv = __ldg(&g_dinv[warp]);
    float d2 = dv * dv;
    float4 hv = __ldg((const float4*)(g_h1 + (size_t)warp * HID) + q);
    float4 r4;
    r4.x = fmaxf(acc.x + d2 * hv.x + b1s[q * 4 + 0], 0.0f);
    r4.y = fmaxf(acc.y + d2 * hv.y + b1s[q * 4 + 1], 0.0f);
    r4.z = fmaxf(acc.z + d2 * hv.z + b1s[q * 4 + 2], 0.0f);
    r4.w = fmaxf(acc.w + d2 * hv.w + b1s[q * 4 + 3], 0.0f);

    // GEMM2 within warp: lane j (j = lane & 7) computes output column j
    float racc = 0.0f;
    int j = lane & 7;
    #pragma unroll
    for (int qq = 0; qq < 4; qq++) {
        float rx = __shfl_sync(0xffffffffu, r4.x, qq);
        float ry = __shfl_sync(0xffffffffu, r4.y, qq);
        float rz = __shfl_sync(0xffffffffu, r4.z, qq);
        float rw = __shfl_sync(0xffffffffu, r4.w, qq);
        racc = fmaf(rx, Ws2[(qq * 4 + 0) * HID2 + j], racc);
        racc = fmaf(ry, Ws2[(qq * 4 + 1) * HID2 + j], racc);
        racc = fmaf(rz, Ws2[(qq * 4 + 2) * HID2 + j], racc);
        racc = fmaf(rw, Ws2[(qq * 4 + 3) * HID2 + j], racc);
    }
    if (lane < 8) g_h2[(size_t)warp * HID2 + lane] = racc;   // col 7 -> 0 via pad
}

// ---------------- gather layer 2 + finalize -> out ----------------
__global__ void k_gather2(const float* __restrict__ b2, float* __restrict__ out) {
    int warp = (blockIdx.x * GTPB + threadIdx.x) >> 5;
    if (warp >= N_NODES) return;
    int lane = threadIdx.x & 31;
    int eslot = lane >> 1;          // 0..15
    int half  = lane & 1;

    int beg = __ldg(&g_off[warp]);
    int end = __ldg(&g_off[warp + 1]);

    float4 acc = make_float4(0.f, 0.f, 0.f, 0.f);
    for (int e = beg + eslot; e < end; e += 16) {
        uint2 ent = __ldg(&g_csr[e]);
        float w = __uint_as_float(ent.y);
        float4 v = __ldg((const float4*)(g_h2 + (size_t)ent.x * HID2) + half);
        acc.x = fmaf(v.x, w, acc.x);
        acc.y = fmaf(v.y, w, acc.y);
        acc.z = fmaf(v.z, w, acc.z);
        acc.w = fmaf(v.w, w, acc.w);
    }
    #pragma unroll
    for (int m = 2; m <= 16; m <<= 1) {
        acc.x += __shfl_xor_sync(0xffffffffu, acc.x, m);
        acc.y += __shfl_xor_sync(0xffffffffu, acc.y, m);
        acc.z += __shfl_xor_sync(0xffffffffu, acc.z, m);
        acc.w += __shfl_xor_sync(0xffffffffu, acc.w, m);
    }
    if (lane < 2) {
        float dv = __ldg(&g_dinv[warp]);
        float d2 = dv * dv;
        float4 hv = *((const float4*)(g_h2 + (size_t)warp * HID2) + half);
        float o0 = acc.x + d2 * hv.x;
        float o1 = acc.y + d2 * hv.y;
        float o2 = acc.z + d2 * hv.z;
        float o3 = acc.w + d2 * hv.w;
        float* op = out + (size_t)warp * CLS + half * 4;
        if (half == 0) {
            op[0] = o0 + __ldg(&b2[0]);
            op[1] = o1 + __ldg(&b2[1]);
            op[2] = o2 + __ldg(&b2[2]);
            op[3] = o3 + __ldg(&b2[3]);
        } else {
            op[0] = o0 + __ldg(&b2[4]);
            op[1] = o1 + __ldg(&b2[5]);
            op[2] = o2 + __ldg(&b2[6]);
        }
    }
}

// ---------------- launch: SINGLE stream; gemm1 issued 4th for ncu ---------
extern "C" void kernel_launch(void* const* d_in, const int* in_sizes, int n_in,
                              void* d_out, int out_size) {
    const float* x  = (const float*)d_in[0];
    const void*  ei = d_in[1];
    const float* W1 = (const float*)d_in[2];
    const float* b1 = (const float*)d_in[3];
    const float* W2 = (const float*)d_in[4];
    const float* b2 = (const float*)d_in[5];
    float* out = (float*)d_out;

    int E = in_sizes[1] / 2;

    const int TPB = 256;
    int nbE  = (E + TPB - 1) / TPB;
    int nbG  = (N_NODES * 32 + GTPB - 1) / GTPB;
    int nbG1 = (N_NODES + G1_TPB - 1) / G1_TPB;

    k_detect_zero<<<NB_NODE, TPB>>>((const unsigned int*)ei);
    k_deg   <<<nbE, TPB>>>(ei, E);
    k_scan1 <<<NB_NODE, TPB>>>();
    k_gemm1 <<<nbG1, G1_TPB>>>(x, W1);      // 4th issued launch -> ncu target
    k_scan3 <<<NB_NODE, TPB>>>(E);
    k_build <<<nbE, TPB>>>(ei, E);
    k_gather1<<<nbG, GTPB>>>(b1, W2);
    k_gather2<<<nbG, GTPB>>>(b2, out);
}

// round 15
// speedup vs baseline: 1.3212x; 1.0347x over previous
#include <cuda_runtime.h>

#define N_NODES 100000
#define F_IN 512
#define HID 16
#define CLS 7
#define HID2 8
#define E_MAX 3400000
#define NB_NODE 391          // ceil(100000/256)

typedef unsigned long long ull;

// ---------------- device scratch ----------------
__device__ int   g_degi[N_NODES];
__device__ int   g_off [N_NODES + 1];
__device__ int   g_cur [N_NODES];
__device__ int   g_bsum[512];
__device__ float g_dinv[N_NODES];
__device__ __align__(16) float g_h1 [N_NODES * HID];
__device__ __align__(16) float g_h2 [N_NODES * HID2];
__device__ __align__(16) uint2 g_csr[E_MAX];           // {src, bits(weight)}
__device__ int g_is64;

// ---- f32x2 helpers (Blackwell packed fp32 pipe) ----
__device__ __forceinline__ ull fma2(ull a, ull b, ull c) {
    ull d;
    asm("fma.rn.f32x2 %0, %1, %2, %3;" : "=l"(d) : "l"(a), "l"(b), "l"(c));
    return d;
}
__device__ __forceinline__ ull pack2(float a) {
    ull p;
    asm("mov.b64 %0, {%1, %1};" : "=l"(p) : "f"(a));
    return p;
}
__device__ __forceinline__ void unpack2(ull p, float& lo, float& hi) {
    asm("mov.b64 {%0, %1}, %2;" : "=f"(lo), "=f"(hi) : "l"(p));
}
union F4U { float4 f; ull u[2]; };

// ---- cp.async helpers ----
__device__ __forceinline__ void cp16(void* smem_dst, const void* gmem_src) {
    unsigned s = (unsigned)__cvta_generic_to_shared(smem_dst);
    asm volatile("cp.async.cg.shared.global [%0], [%1], 16;" :: "r"(s), "l"(gmem_src));
}
__device__ __forceinline__ void cp_commit() {
    asm volatile("cp.async.commit_group;");
}
__device__ __forceinline__ void cp_wait1() {
    asm volatile("cp.async.wait_group 1;");
}

// ---------------- detect dtype + zero degrees (fused) ----------------
__global__ void k_detect_zero(const unsigned int* __restrict__ w) {
    int i = blockIdx.x * blockDim.x + threadIdx.x;
    if (i < N_NODES) g_degi[i] = 0;
    if (i == 0) {
        int all0 = 1;
        #pragma unroll 1
        for (int k = 0; k < 64; k++) {
            long idx = 2L * k * 50001L + 1L;
            if (w[idx] != 0u) all0 = 0;
        }
        g_is64 = all0;
    }
}

// ======== FAT KERNEL: gemm1 blocks + deg blocks in one launch ============
#define G1_TPB  128
#define KC      32
#define NCHUNK  (F_IN / KC)    // 16
#define XS2     36             // 32 + 4 pad: conflict-free LDS.128

__global__ void __launch_bounds__(G1_TPB)
k_fat(const float* __restrict__ x, const float* __restrict__ W1,
      const void* __restrict__ ei, int E, int nbGemm) {
    __shared__ __align__(16) float xs[2][G1_TPB * XS2];   // 2 x 18 KB
    __shared__ __align__(16) float ws[2][KC * HID];       // 2 x 2 KB

    int t = threadIdx.x;

    if (blockIdx.x >= nbGemm) {
        // ---- deg role: count in-degree ----
        int i = (blockIdx.x - nbGemm) * G1_TPB + t;
        if (i < E) {
            int dst;
            if (g_is64) dst = (int)__ldg(&((const long long*)ei)[(size_t)E + i]);
            else        dst = __ldg(&((const int*)ei)[(size_t)E + i]);
            atomicAdd(&g_degi[dst], 1);
        }
        return;
    }

    // ---- gemm1 role: h1 = x @ W1, cp.async double-buffered, f32x2 ----
    int rowbase = blockIdx.x * G1_TPB;

    ull acc[8];
    #pragma unroll
    for (int j = 0; j < 8; j++) acc[j] = 0ULL;

    auto issue = [&](int ch, int buf) {
        cp16(&ws[buf][t * 4], (const float4*)(W1 + ch * KC * HID) + t);
        #pragma unroll
        for (int i = 0; i < 8; i++) {
            int f   = t + i * G1_TPB;
            int row = f >> 3;              // 8 float4 per row
            int c4  = f & 7;
            int grow = rowbase + row;
            if (grow >= N_NODES) grow = N_NODES - 1;
            cp16(&xs[buf][row * XS2 + c4 * 4],
                 (const float4*)(x + (size_t)grow * F_IN + ch * KC) + c4);
        }
    };

    issue(0, 0);
    cp_commit();

    #pragma unroll 1
    for (int ch = 0; ch < NCHUNK; ch++) {
        if (ch + 1 < NCHUNK) issue(ch + 1, (ch + 1) & 1);
        cp_commit();
        cp_wait1();               // oldest group (chunk ch) complete
        __syncthreads();

        int cb = ch & 1;
        #pragma unroll
        for (int k4 = 0; k4 < KC / 4; k4++) {
            float4 xv = *(const float4*)&xs[cb][t * XS2 + k4 * 4];
            #pragma unroll
            for (int kk = 0; kk < 4; kk++) {
                const float4* wq = (const float4*)&ws[cb][(k4 * 4 + kk) * HID];
                F4U wa, wb, wc, wd;
                wa.f = wq[0]; wb.f = wq[1]; wc.f = wq[2]; wd.f = wq[3];
                ull p = pack2(((const float*)&xv)[kk]);
                acc[0] = fma2(p, wa.u[0], acc[0]);
                acc[1] = fma2(p, wa.u[1], acc[1]);
                acc[2] = fma2(p, wb.u[0], acc[2]);
                acc[3] = fma2(p, wb.u[1], acc[3]);
                acc[4] = fma2(p, wc.u[0], acc[4]);
                acc[5] = fma2(p, wc.u[1], acc[5]);
                acc[6] = fma2(p, wd.u[0], acc[6]);
                acc[7] = fma2(p, wd.u[1], acc[7]);
            }
        }
        __syncthreads();
    }

    int row = rowbase + t;
    if (row < N_NODES) {
        float4* o = (float4*)(g_h1 + (size_t)row * HID);
        #pragma unroll
        for (int q = 0; q < 4; q++) {
            float a, b, c, d;
            unpack2(acc[q * 2],     a, b);
            unpack2(acc[q * 2 + 1], c, d);
            o[q] = make_float4(a, b, c, d);
        }
    }
}

// ---------------- scan stage 1: per-block exclusive scan ----------------
__global__ void k_scan1() {
    __shared__ int s[256];
    int b = blockIdx.x, t = threadIdx.x;
    int i = b * 256 + t;
    int v = (i < N_NODES) ? g_degi[i] : 0;
    s[t] = v; __syncthreads();
    #pragma unroll
    for (int d = 1; d < 256; d <<= 1) {
        int add = (t >= d) ? s[t - d] : 0;
        __syncthreads();
        s[t] += add;
        __syncthreads();
    }
    if (i < N_NODES) g_off[i] = s[t] - v;   // local exclusive
    if (t == 255) g_bsum[b] = s[255];
}

// ---------------- scan stage 2 (block offsets per-block) + dinv ----------
__global__ void k_scan3(int E) {
    __shared__ int sb[256];
    int t = threadIdx.x, b = blockIdx.x;
    int part = 0;
    for (int j = t; j < b; j += 256) part += g_bsum[j];
    sb[t] = part; __syncthreads();
    #pragma unroll
    for (int d = 128; d > 0; d >>= 1) {
        if (t < d) sb[t] += sb[t + d];
        __syncthreads();
    }
    int boff = sb[0];
    int i = b * 256 + t;
    if (i < N_NODES) {
        int off = g_off[i] + boff;
        g_off[i] = off;
        g_cur[i] = off;
        g_dinv[i] = rsqrtf((float)(g_degi[i] + 1));  // +1 self loop
        if (i == N_NODES - 1) g_off[N_NODES] = E;
    }
}

// ---------------- CSR build: scatter {src, weight} by dst ----------------
__global__ void k_build(const void* __restrict__ ei, int E) {
    int i = blockIdx.x * blockDim.x + threadIdx.x;
    if (i >= E) return;
    int src, dst;
    if (g_is64) {
        const long long* e = (const long long*)ei;
        src = (int)__ldg(&e[i]); dst = (int)__ldg(&e[(size_t)E + i]);
    } else {
        const int* e = (const int*)ei;
        src = __ldg(&e[i]); dst = __ldg(&e[(size_t)E + i]);
    }
    float w = __ldg(&g_dinv[src]) * __ldg(&g_dinv[dst]);
    int pos = atomicAdd(&g_cur[dst], 1);
    g_csr[pos] = make_uint2((unsigned)src, __float_as_uint(w));
}

// ------- gather layer 1 + selfloop + bias + relu + GEMM2 -> h2 (fused) -----
#define GTPB 256
__global__ void k_gather1(const float* __restrict__ b1, const float* __restrict__ W2) {
    __shared__ float Ws2[HID * HID2];   // W2 padded to 8 cols (col 7 = 0)
    __shared__ float b1s[HID];
    if (threadIdx.x < HID * HID2) {
        int k = threadIdx.x >> 3, j = threadIdx.x & 7;
        Ws2[threadIdx.x] = (j < CLS) ? __ldg(&W2[k * CLS + j]) : 0.0f;
    }
    if (threadIdx.x < HID) b1s[threadIdx.x] = __ldg(&b1[threadIdx.x]);
    __syncthreads();

    int warp = (blockIdx.x * GTPB + threadIdx.x) >> 5;
    if (warp >= N_NODES) return;
    int lane = threadIdx.x & 31;
    int eslot = lane >> 2;          // 0..7
    int q     = lane & 3;           // float4 chunk 0..3

    int beg = __ldg(&g_off[warp]);
    int end = __ldg(&g_off[warp + 1]);

    float4 acc = make_float4(0.f, 0.f, 0.f, 0.f);
    for (int e = beg + eslot; e < end; e += 8) {
        uint2 ent = __ldg(&g_csr[e]);
        float w = __uint_as_float(ent.y);
        float4 v = __ldg((const float4*)(g_h1 + (size_t)ent.x * HID) + q);
        acc.x = fmaf(v.x, w, acc.x);
        acc.y = fmaf(v.y, w, acc.y);
        acc.z = fmaf(v.z, w, acc.z);
        acc.w = fmaf(v.w, w, acc.w);
    }
    #pragma unroll
    for (int m = 4; m <= 16; m <<= 1) {
        acc.x += __shfl_xor_sync(0xffffffffu, acc.x, m);
        acc.y += __shfl_xor_sync(0xffffffffu, acc.y, m);
        acc.z += __shfl_xor_sync(0xffffffffu, acc.z, m);
        acc.w += __shfl_xor_sync(0xffffffffu, acc.w, m);
    }
    float dv = __ldg(&g_dinv[warp]);
    float d2 = dv * dv;
    float4 hv = __ldg((const float4*)(g_h1 + (size_t)warp * HID) + q);
    float4 r4;
    r4.x = fmaxf(acc.x + d2 * hv.x + b1s[q * 4 + 0], 0.0f);
    r4.y = fmaxf(acc.y + d2 * hv.y + b1s[q * 4 + 1], 0.0f);
    r4.z = fmaxf(acc.z + d2 * hv.z + b1s[q * 4 + 2], 0.0f);
    r4.w = fmaxf(acc.w + d2 * hv.w + b1s[q * 4 + 3], 0.0f);

    // GEMM2 within warp: lane j (j = lane & 7) computes output column j
    float racc = 0.0f;
    int j = lane & 7;
    #pragma unroll
    for (int qq = 0; qq < 4; qq++) {
        float rx = __shfl_sync(0xffffffffu, r4.x, qq);
        float ry = __shfl_sync(0xffffffffu, r4.y, qq);
        float rz = __shfl_sync(0xffffffffu, r4.z, qq);
        float rw = __shfl_sync(0xffffffffu, r4.w, qq);
        racc = fmaf(rx, Ws2[(qq * 4 + 0) * HID2 + j], racc);
        racc = fmaf(ry, Ws2[(qq * 4 + 1) * HID2 + j], racc);
        racc = fmaf(rz, Ws2[(qq * 4 + 2) * HID2 + j], racc);
        racc = fmaf(rw, Ws2[(qq * 4 + 3) * HID2 + j], racc);
    }
    if (lane < 8) g_h2[(size_t)warp * HID2 + lane] = racc;   // col 7 -> 0 via pad
}

// ---------------- gather layer 2 + finalize -> out ----------------
__global__ void k_gather2(const float* __restrict__ b2, float* __restrict__ out) {
    int warp = (blockIdx.x * GTPB + threadIdx.x) >> 5;
    if (warp >= N_NODES) return;
    int lane = threadIdx.x & 31;
    int eslot = lane >> 1;          // 0..15
    int half  = lane & 1;

    int beg = __ldg(&g_off[warp]);
    int end = __ldg(&g_off[warp + 1]);

    float4 acc = make_float4(0.f, 0.f, 0.f, 0.f);
    for (int e = beg + eslot; e < end; e += 16) {
        uint2 ent = __ldg(&g_csr[e]);
        float w = __uint_as_float(ent.y);
        float4 v = __ldg((const float4*)(g_h2 + (size_t)ent.x * HID2) + half);
        acc.x = fmaf(v.x, w, acc.x);
        acc.y = fmaf(v.y, w, acc.y);
        acc.z = fmaf(v.z, w, acc.z);
        acc.w = fmaf(v.w, w, acc.w);
    }
    #pragma unroll
    for (int m = 2; m <= 16; m <<= 1) {
        acc.x += __shfl_xor_sync(0xffffffffu, acc.x, m);
        acc.y += __shfl_xor_sync(0xffffffffu, acc.y, m);
        acc.z += __shfl_xor_sync(0xffffffffu, acc.z, m);
        acc.w += __shfl_xor_sync(0xffffffffu, acc.w, m);
    }
    if (lane < 2) {
        float dv = __ldg(&g_dinv[warp]);
        float d2 = dv * dv;
        float4 hv = *((const float4*)(g_h2 + (size_t)warp * HID2) + half);
        float o0 = acc.x + d2 * hv.x;
        float o1 = acc.y + d2 * hv.y;
        float o2 = acc.z + d2 * hv.z;
        float o3 = acc.w + d2 * hv.w;
        float* op = out + (size_t)warp * CLS + half * 4;
        if (half == 0) {
            op[0] = o0 + __ldg(&b2[0]);
            op[1] = o1 + __ldg(&b2[1]);
            op[2] = o2 + __ldg(&b2[2]);
            op[3] = o3 + __ldg(&b2[3]);
        } else {
            op[0] = o0 + __ldg(&b2[4]);
            op[1] = o1 + __ldg(&b2[5]);
            op[2] = o2 + __ldg(&b2[6]);
        }
    }
}

// ---------------- launch: single stream, fat kernel overlap ---------------
extern "C" void kernel_launch(void* const* d_in, const int* in_sizes, int n_in,
                              void* d_out, int out_size) {
    const float* x  = (const float*)d_in[0];
    const void*  ei = d_in[1];
    const float* W1 = (const float*)d_in[2];
    const float* b1 = (const float*)d_in[3];
    const float* W2 = (const float*)d_in[4];
    const float* b2 = (const float*)d_in[5];
    float* out = (float*)d_out;

    int E = in_sizes[1] / 2;

    const int TPB = 256;
    int nbE   = (E + TPB - 1) / TPB;
    int nbG   = (N_NODES * 32 + GTPB - 1) / GTPB;
    int nbG1  = (N_NODES + G1_TPB - 1) / G1_TPB;          // 782 gemm blocks
    int nbDeg = (E + G1_TPB - 1) / G1_TPB;                // deg blocks (128 thr)

    k_detect_zero<<<NB_NODE, TPB>>>((const unsigned int*)ei);
    k_fat   <<<nbG1 + nbDeg, G1_TPB>>>(x, W1, ei, E, nbG1);  // gemm1 + deg overlapped
    k_scan1 <<<NB_NODE, TPB>>>();
    k_scan3 <<<NB_NODE, TPB>>>(E);
    k_build <<<nbE, TPB>>>(ei, E);
    k_gather1<<<nbG, GTPB>>>(b1, W2);
    k_gather2<<<nbG, GTPB>>>(b2, out);
}